// round 11
// baseline (speedup 1.0000x reference)
#include <cuda_runtime.h>
#include <cuda_fp16.h>
#include <cstdint>
#include <math.h>

#define NROWS 262144
#define C 256
#define S 16

#define BM 128
#define BK 64
#define NCHUNK 4            // K=256 / BK
#define NT 512              // threads per CTA
#define NTILE (NROWS / BM)  // 2048
#define GRID 148
#define AP 72               // A smem row stride in halves (64 + 8 pad)
#define BP 264              // B smem row stride in halves (256 + 8 pad)

// ---------------- scratch ---------------------------------------------------
__device__ float g_segsum[S * C];
__device__ float g_ctab[S * C];
// B image: [chunk][k=64][BP] fp16 of (W1a * diag(bn_scale)), exact smem layout
__device__ __half g_Bimg[NCHUNK * BK * BP];

// ---------------- helpers ---------------------------------------------------
__device__ __forceinline__ uint32_t smem_u32(const void* p) {
    uint32_t a;
    asm("{ .reg .u64 t; cvta.to.shared.u64 t, %1; cvt.u32.u64 %0, t; }" : "=r"(a) : "l"(p));
    return a;
}
#define CP_ASYNC16(dst, src) asm volatile("cp.async.cg.shared.global [%0], [%1], 16;" :: "r"(dst), "l"(src))
#define CP_COMMIT() asm volatile("cp.async.commit_group;" ::: "memory")
#define CP_WAIT0()  asm volatile("cp.async.wait_group 0;" ::: "memory")
#define BAR_HALF(id) asm volatile("bar.sync %0, 256;" :: "r"(id) : "memory")

#define LDSM_X4(r0, r1, r2, r3, addr) \
    asm volatile("ldmatrix.sync.aligned.m8n8.x4.shared.b16 {%0,%1,%2,%3}, [%4];" \
                 : "=r"(r0), "=r"(r1), "=r"(r2), "=r"(r3) : "r"(addr))
#define LDSM_X2_T(r0, r1, addr) \
    asm volatile("ldmatrix.sync.aligned.m8n8.x2.trans.shared.b16 {%0,%1}, [%2];" \
                 : "=r"(r0), "=r"(r1) : "r"(addr))

#define MMA_F16(d, a, b) \
    asm volatile("mma.sync.aligned.m16n8k16.row.col.f32.f16.f16.f32 " \
                 "{%0,%1,%2,%3}, {%4,%5,%6,%7}, {%8,%9}, {%0,%1,%2,%3};" \
                 : "+f"((d)[0]), "+f"((d)[1]), "+f"((d)[2]), "+f"((d)[3]) \
                 : "r"((a)[0]), "r"((a)[1]), "r"((a)[2]), "r"((a)[3]), "r"((b)[0]), "r"((b)[1]))

// ---------------------------------------------------------------------------
// kw: W1a rows scaled by BN scale per column, fp16 chunk images; zeros segsum
__global__ void kw_split(const float* __restrict__ W1,
                         const float* __restrict__ gamma,
                         const float* __restrict__ rv) {
    int k = blockIdx.x;   // 0..255
    int n = threadIdx.x;  // 0..255
    if (k < S) g_segsum[k * C + n] = 0.0f;
    float sc = gamma[n] * rsqrtf(rv[n] + 1e-5f);
    float w = W1[k * C + n] * sc;
    int c = k >> 6, kk = k & 63;
    g_Bimg[(c * BK + kk) * BP + n] = __float2half_rn(w);
    if (n < BP - 256)
        g_Bimg[(c * BK + kk) * BP + 256 + n] = __float2half_rn(0.0f);
}

// ---------------------------------------------------------------------------
// k1: segment sums, float4 per thread, CTA-uniform fast path.
// 256 threads: cg = tid&63 (float4 column group), rsub = tid>>6 (row phase).
// ---------------------------------------------------------------------------
__global__ void __launch_bounds__(256) k1_segsum(const float* __restrict__ x,
                                                 const int* __restrict__ o32) {
    __shared__ int so[S];
    __shared__ float4 red[256];
    int tid = threadIdx.x;
    if (tid < S) {
        int stride = (o32[1] == 0) ? 2 : 1;
        so[tid] = o32[tid * stride];
    }
    __syncthreads();

    int g0 = blockIdx.x * 128;
    int cg = tid & 63;
    int rsub = tid >> 6;

    int sa = 0;
    while (g0 >= so[sa]) sa++;
    int sb = sa;
    while (g0 + 127 >= so[sb]) sb++;

    const float4* xp = (const float4*)x + (size_t)(g0 + rsub) * 64 + cg;
    float4 acc = make_float4(0.f, 0.f, 0.f, 0.f);

    if (sa == sb) {
        // whole CTA inside one segment: branch-free
#pragma unroll 4
        for (int i = 0; i < 32; i++) {
            float4 v = __ldg(xp + (size_t)i * 256);
            acc.x += v.x; acc.y += v.y; acc.z += v.z; acc.w += v.w;
        }
        red[tid] = acc;
        __syncthreads();
        if (tid < 64) {
            float4 a0 = red[tid], a1 = red[64 + tid], a2 = red[128 + tid], a3 = red[192 + tid];
            float* dst = &g_segsum[sa * C + tid * 4];
            atomicAdd(dst + 0, a0.x + a1.x + a2.x + a3.x);
            atomicAdd(dst + 1, a0.y + a1.y + a2.y + a3.y);
            atomicAdd(dst + 2, a0.z + a1.z + a2.z + a3.z);
            atomicAdd(dst + 3, a0.w + a1.w + a2.w + a3.w);
        }
    } else {
        // boundary CTA (rare): per-row segment tracking
        int s = sa;
        while (g0 + rsub >= so[s]) s++;
        for (int i = 0; i < 32; i++) {
            int row = g0 + rsub + 4 * i;
            if (row >= so[s]) {
                float* dst = &g_segsum[s * C + cg * 4];
                atomicAdd(dst + 0, acc.x);
                atomicAdd(dst + 1, acc.y);
                atomicAdd(dst + 2, acc.z);
                atomicAdd(dst + 3, acc.w);
                acc = make_float4(0.f, 0.f, 0.f, 0.f);
                while (row >= so[s]) s++;
            }
            float4 v = __ldg(xp + (size_t)i * 256);
            acc.x += v.x; acc.y += v.y; acc.z += v.z; acc.w += v.w;
        }
        float* dst = &g_segsum[s * C + cg * 4];
        atomicAdd(dst + 0, acc.x);
        atomicAdd(dst + 1, acc.y);
        atomicAdd(dst + 2, acc.z);
        atomicAdd(dst + 3, acc.w);
    }
}

// ---------------------------------------------------------------------------
// k2f: fused per-segment math. grid=S, 512 threads.
// mean -> h = relu(mean@W2 + b2) -> ctab = (h@W1b + b1)*sc + beta - rm*sc
// Thread layout per pass: col0 = tid&63, kc = tid>>6 (8-way k split).
// ---------------------------------------------------------------------------
__global__ void __launch_bounds__(512) k2f(const int* __restrict__ o32,
                                           const float* __restrict__ W2,
                                           const float* __restrict__ b2,
                                           const float* __restrict__ W1,
                                           const float* __restrict__ b1,
                                           const float* __restrict__ gamma,
                                           const float* __restrict__ beta,
                                           const float* __restrict__ rm,
                                           const float* __restrict__ rv) {
    __shared__ float mean_s[C];
    __shared__ float h_s[C];
    __shared__ float red[512];
    int s = blockIdx.x, tid = threadIdx.x;
    int stride = (o32[1] == 0) ? 2 : 1;
    int oe = o32[s * stride];
    int ob = (s > 0) ? o32[(s - 1) * stride] : 0;
    float inv = 1.0f / (float)(oe - ob);
    if (tid < C) mean_s[tid] = g_segsum[s * C + tid] * inv;
    __syncthreads();

    int col0 = tid & 63;
    int kc = tid >> 6;

#pragma unroll 1
    for (int p = 0; p < 4; p++) {
        int col = p * 64 + col0;
        float a = 0.0f;
#pragma unroll 8
        for (int i = 0; i < 32; i++)
            a = fmaf(mean_s[kc * 32 + i], __ldg(&W2[(size_t)(kc * 32 + i) * C + col]), a);
        red[tid] = a;
        __syncthreads();
        if (tid < 64) {
            float t = red[tid];
#pragma unroll
            for (int j = 1; j < 8; j++) t += red[j * 64 + tid];
            int c0 = p * 64 + tid;
            h_s[c0] = fmaxf(t + __ldg(&b2[c0]), 0.0f);
        }
        __syncthreads();
    }

#pragma unroll 1
    for (int p = 0; p < 4; p++) {
        int col = p * 64 + col0;
        float a = 0.0f;
#pragma unroll 8
        for (int i = 0; i < 32; i++)
            a = fmaf(h_s[kc * 32 + i], __ldg(&W1[(size_t)(C + kc * 32 + i) * C + col]), a);
        red[tid] = a;
        __syncthreads();
        if (tid < 64) {
            float t = red[tid];
#pragma unroll
            for (int j = 1; j < 8; j++) t += red[j * 64 + tid];
            int c0 = p * 64 + tid;
            float sc = gamma[c0] * rsqrtf(rv[c0] + 1e-5f);
            g_ctab[s * C + c0] = (t + __ldg(&b1[c0])) * sc + beta[c0] - rm[c0] * sc;
        }
        __syncthreads();
    }
}

// ---------------------------------------------------------------------------
// k3: persistent fp16 mma.sync GEMM, B + ctab resident in smem, CTA split into
// two independent 256-thread halves synced by named barriers.
// smem: [so 128B][ctab 16K][A: 2 buf x 128 x AP halves][B: 4 x 64 x BP halves]
// ---------------------------------------------------------------------------
#define A_BYTES (BM * AP * 2)          // 18432
#define B_BYTES (BK * BP * 2)          // 33792 per chunk
#define CT_OFF 128
#define A_OFF (CT_OFF + 16384)         // 16512
#define B_OFF (A_OFF + 2 * A_BYTES)    // 53376
#define K3_SMEM (B_OFF + NCHUNK * B_BYTES)  // 188544

__global__ void __launch_bounds__(NT, 1) k3_mma(const float* __restrict__ x,
                                                const int* __restrict__ o32,
                                                float* __restrict__ out) {
    extern __shared__ char smem[];
    uint32_t sbase = smem_u32(smem);
    int* so_s = (int*)smem;
    float* ct_s = (float*)(smem + CT_OFF);
    __half* Asm = (__half*)(smem + A_OFF);
    const uint32_t aA = sbase + A_OFF;
    const uint32_t aB = sbase + B_OFF;

    int tid = threadIdx.x;
    int lane = tid & 31;
    int wid = tid >> 5;
    int wm = wid >> 3;   // 0..1 : which half
    int wn = wid & 7;    // 0..7
    int barid = 1 + wm;  // named barrier per half

    if (tid < S) {
        int stride = (o32[1] == 0) ? 2 : 1;
        so_s[tid] = o32[tid * stride];
    }
    // ctab -> smem (16 KB)
    {
        const float4* src = (const float4*)g_ctab;
        float4* dst = (float4*)ct_s;
        dst[tid] = __ldg(&src[tid]);
        dst[tid + NT] = __ldg(&src[tid + NT]);
    }
    // ---- load ALL of B once (135 KB) ----
    {
        const char* src = (const char*)g_Bimg;
        for (int i = tid; i < (NCHUNK * B_BYTES) / 16; i += NT)
            CP_ASYNC16(aB + (uint32_t)(i * 16), src + i * 16);
        CP_COMMIT();
    }

    int arow = tid >> 2;         // 0..127
    int acol = (tid & 3) * 16;

    uint32_t aoff[4];
#pragma unroll
    for (int ms = 0; ms < 4; ms++)
        aoff[ms] = (uint32_t)(((wm * 64 + ms * 16 + (lane & 15)) * AP + ((lane >> 4) << 3)) * 2);
    uint32_t boff[4];
#pragma unroll
    for (int ns = 0; ns < 4; ns++)
        boff[ns] = (uint32_t)(((lane & 15) * BP + wn * 32 + ns * 8) * 2);

    float acc[4][4][4];
#pragma unroll
    for (int i = 0; i < 4; i++)
#pragma unroll
        for (int j = 0; j < 4; j++)
#pragma unroll
            for (int r = 0; r < 4; r++) acc[i][j][r] = 0.0f;

    int ntile_local = 0;
    for (int t = blockIdx.x; t < NTILE; t += GRID) ntile_local++;
    int ncc = ntile_local * NCHUNK;
    if (ncc == 0) return;

    // prologue: load A for cc=0
    float4 pre[4];
    {
        const float* ag = x + (size_t)((size_t)blockIdx.x * BM + arow) * C + acol;
#pragma unroll
        for (int j = 0; j < 4; j++) pre[j] = __ldg((const float4*)(ag + j * 4));
        __half* dst = Asm + (size_t)arow * AP + acol;
#pragma unroll
        for (int j = 0; j < 4; j++) {
            __half2 a = __float22half2_rn(make_float2(pre[j].x, pre[j].y));
            __half2 b = __float22half2_rn(make_float2(pre[j].z, pre[j].w));
            *(uint2*)(dst + j * 4) = make_uint2(*(uint32_t*)&a, *(uint32_t*)&b);
        }
    }
    CP_WAIT0();
    __syncthreads();   // B + ctab + so + A(0) visible; halves drift after this

#pragma unroll 1
    for (int cc = 0; cc < ncc; cc++) {
        int chunk = cc & (NCHUNK - 1);
        int tile_i = cc >> 2;
        int buf = cc & 1;
        uint32_t abuf = aA + (uint32_t)(buf * A_BYTES);
        uint32_t bbuf = aB + (uint32_t)(chunk * B_BYTES);

        if (cc < ncc - 1) {
            int nchunk = (cc + 1) & (NCHUNK - 1);
            int ntile = (cc + 1) >> 2;
            size_t grow = (size_t)(blockIdx.x + ntile * GRID) * BM + arow;
            const float* ag = x + grow * C + nchunk * BK + acol;
#pragma unroll
            for (int j = 0; j < 4; j++) pre[j] = __ldg((const float4*)(ag + j * 4));
        }

#pragma unroll
        for (int kk = 0; kk < BK; kk += 16) {
            uint32_t bf[4][2];
#pragma unroll
            for (int ns = 0; ns < 4; ns++)
                LDSM_X2_T(bf[ns][0], bf[ns][1], bbuf + boff[ns] + (uint32_t)(kk * BP * 2));
#pragma unroll
            for (int ms = 0; ms < 4; ms++) {
                uint32_t af[4];
                LDSM_X4(af[0], af[1], af[2], af[3], abuf + aoff[ms] + (uint32_t)(kk * 2));
#pragma unroll
                for (int ns = 0; ns < 4; ns++) MMA_F16(acc[ms][ns], af, bf[ns]);
            }
        }

        if (cc < ncc - 1) {
            __half* dst = Asm + (size_t)((buf ^ 1) * (A_BYTES / 2)) + (size_t)arow * AP + acol;
#pragma unroll
            for (int j = 0; j < 4; j++) {
                __half2 a = __float22half2_rn(make_float2(pre[j].x, pre[j].y));
                __half2 b = __float22half2_rn(make_float2(pre[j].z, pre[j].w));
                *(uint2*)(dst + j * 4) = make_uint2(*(uint32_t*)&a, *(uint32_t*)&b);
            }
        }
        BAR_HALF(barid);

        if (chunk == NCHUNK - 1) {
            int m0 = (blockIdx.x + tile_i * GRID) * BM;
            int r0 = lane >> 2;
            int cq = (lane & 3) * 2;
#pragma unroll
            for (int ms = 0; ms < 4; ms++) {
                int row = m0 + wm * 64 + ms * 16 + r0;
                int s0 = 0, s1 = 0;
                while (row >= so_s[s0]) s0++;
                while (row + 8 >= so_s[s1]) s1++;
                const float* ct0 = ct_s + s0 * C;
                const float* ct1 = ct_s + s1 * C;
                float* o0 = out + (size_t)row * C;
                float* o1 = out + (size_t)(row + 8) * C;
#pragma unroll
                for (int ns = 0; ns < 4; ns++) {
                    int col = wn * 32 + ns * 8 + cq;
                    float2 ca = *(const float2*)&ct0[col];
                    float2 cb = *(const float2*)&ct1[col];
                    float2 va, vb;
                    va.x = fmaxf(acc[ms][ns][0] + ca.x, 0.0f);
                    va.y = fmaxf(acc[ms][ns][1] + ca.y, 0.0f);
                    vb.x = fmaxf(acc[ms][ns][2] + cb.x, 0.0f);
                    vb.y = fmaxf(acc[ms][ns][3] + cb.y, 0.0f);
                    *(float2*)&o0[col] = va;
                    *(float2*)&o1[col] = vb;
                    acc[ms][ns][0] = 0.0f; acc[ms][ns][1] = 0.0f;
                    acc[ms][ns][2] = 0.0f; acc[ms][ns][3] = 0.0f;
                }
            }
        }
    }
}

// ---------------------------------------------------------------------------
extern "C" void kernel_launch(void* const* d_in, const int* in_sizes, int n_in,
                              void* d_out, int out_size) {
    const float* x     = (const float*)d_in[0];
    const int*   o     = (const int*)d_in[1];
    const float* W2    = (const float*)d_in[2];
    const float* b2    = (const float*)d_in[3];
    const float* W1    = (const float*)d_in[4];
    const float* b1    = (const float*)d_in[5];
    const float* gamma = (const float*)d_in[6];
    const float* beta  = (const float*)d_in[7];
    const float* rm    = (const float*)d_in[8];
    const float* rv    = (const float*)d_in[9];
    float* out = (float*)d_out;

    cudaFuncSetAttribute(k3_mma, cudaFuncAttributeMaxDynamicSharedMemorySize, K3_SMEM);

    kw_split<<<256, 256>>>(W1, gamma, rv);
    k1_segsum<<<NROWS / 128, 256>>>(x, o);
    k2f<<<S, 512>>>(o, W2, b2, W1, b1, gamma, beta, rm, rv);
    k3_mma<<<GRID, NT, K3_SMEM>>>(x, o, out);
}

// round 12
// speedup vs baseline: 1.2872x; 1.2872x over previous
#include <cuda_runtime.h>
#include <cuda_fp16.h>
#include <cstdint>
#include <math.h>

#define NROWS 262144
#define C 256
#define S 16

#define BM 128
#define BK 64
#define NCHUNK 4            // K=256 / BK
#define NT 256              // threads per CTA (8 warps, warp tile 64x64)
#define NTILE (NROWS / BM)  // 2048
#define GRID 148
#define AP 72               // A smem row stride in halves (64 + 8 pad)
#define BP 264              // B smem row stride in halves (256 + 8 pad)

// ---------------- scratch ---------------------------------------------------
__device__ float g_segsum[S * C];
__device__ float g_ctab[S * C];
// B image: [chunk][k=64][BP] fp16 of (W1a * diag(bn_scale)), exact smem layout
__device__ __half g_Bimg[NCHUNK * BK * BP];

// ---------------- helpers ---------------------------------------------------
__device__ __forceinline__ uint32_t smem_u32(const void* p) {
    uint32_t a;
    asm("{ .reg .u64 t; cvta.to.shared.u64 t, %1; cvt.u32.u64 %0, t; }" : "=r"(a) : "l"(p));
    return a;
}
#define CP_ASYNC16(dst, src) asm volatile("cp.async.cg.shared.global [%0], [%1], 16;" :: "r"(dst), "l"(src))
#define CP_COMMIT() asm volatile("cp.async.commit_group;" ::: "memory")
#define CP_WAIT0()  asm volatile("cp.async.wait_group 0;" ::: "memory")
#define BAR_HALF(id) asm volatile("bar.sync %0, 128;" :: "r"(id) : "memory")

#define LDSM_X4(r0, r1, r2, r3, addr) \
    asm volatile("ldmatrix.sync.aligned.m8n8.x4.shared.b16 {%0,%1,%2,%3}, [%4];" \
                 : "=r"(r0), "=r"(r1), "=r"(r2), "=r"(r3) : "r"(addr))
#define LDSM_X2_T(r0, r1, addr) \
    asm volatile("ldmatrix.sync.aligned.m8n8.x2.trans.shared.b16 {%0,%1}, [%2];" \
                 : "=r"(r0), "=r"(r1) : "r"(addr))

#define MMA_F16(d, a, b) \
    asm volatile("mma.sync.aligned.m16n8k16.row.col.f32.f16.f16.f32 " \
                 "{%0,%1,%2,%3}, {%4,%5,%6,%7}, {%8,%9}, {%0,%1,%2,%3};" \
                 : "+f"((d)[0]), "+f"((d)[1]), "+f"((d)[2]), "+f"((d)[3]) \
                 : "r"((a)[0]), "r"((a)[1]), "r"((a)[2]), "r"((a)[3]), "r"((b)[0]), "r"((b)[1]))

// ---------------------------------------------------------------------------
// kw: W1a rows scaled by BN scale per column, fp16 chunk images; zeros segsum
__global__ void kw_split(const float* __restrict__ W1,
                         const float* __restrict__ gamma,
                         const float* __restrict__ rv) {
    int k = blockIdx.x;   // 0..255
    int n = threadIdx.x;  // 0..255
    if (k < S) g_segsum[k * C + n] = 0.0f;
    float sc = gamma[n] * rsqrtf(rv[n] + 1e-5f);
    float w = W1[k * C + n] * sc;
    int c = k >> 6, kk = k & 63;
    g_Bimg[(c * BK + kk) * BP + n] = __float2half_rn(w);
    if (n < BP - 256)
        g_Bimg[(c * BK + kk) * BP + 256 + n] = __float2half_rn(0.0f);
}

// ---------------------------------------------------------------------------
// k1: segment sums, float4 per thread, CTA-uniform fast path.
// ---------------------------------------------------------------------------
__global__ void __launch_bounds__(256) k1_segsum(const float* __restrict__ x,
                                                 const int* __restrict__ o32) {
    __shared__ int so[S];
    __shared__ float4 red[256];
    int tid = threadIdx.x;
    if (tid < S) {
        int stride = (o32[1] == 0) ? 2 : 1;
        so[tid] = o32[tid * stride];
    }
    __syncthreads();

    int g0 = blockIdx.x * 128;
    int cg = tid & 63;
    int rsub = tid >> 6;

    int sa = 0;
    while (g0 >= so[sa]) sa++;
    int sb = sa;
    while (g0 + 127 >= so[sb]) sb++;

    const float4* xp = (const float4*)x + (size_t)(g0 + rsub) * 64 + cg;
    float4 acc = make_float4(0.f, 0.f, 0.f, 0.f);

    if (sa == sb) {
#pragma unroll 4
        for (int i = 0; i < 32; i++) {
            float4 v = __ldg(xp + (size_t)i * 256);
            acc.x += v.x; acc.y += v.y; acc.z += v.z; acc.w += v.w;
        }
        red[tid] = acc;
        __syncthreads();
        if (tid < 64) {
            float4 a0 = red[tid], a1 = red[64 + tid], a2 = red[128 + tid], a3 = red[192 + tid];
            float* dst = &g_segsum[sa * C + tid * 4];
            atomicAdd(dst + 0, a0.x + a1.x + a2.x + a3.x);
            atomicAdd(dst + 1, a0.y + a1.y + a2.y + a3.y);
            atomicAdd(dst + 2, a0.z + a1.z + a2.z + a3.z);
            atomicAdd(dst + 3, a0.w + a1.w + a2.w + a3.w);
        }
    } else {
        int s = sa;
        while (g0 + rsub >= so[s]) s++;
        for (int i = 0; i < 32; i++) {
            int row = g0 + rsub + 4 * i;
            if (row >= so[s]) {
                float* dst = &g_segsum[s * C + cg * 4];
                atomicAdd(dst + 0, acc.x);
                atomicAdd(dst + 1, acc.y);
                atomicAdd(dst + 2, acc.z);
                atomicAdd(dst + 3, acc.w);
                acc = make_float4(0.f, 0.f, 0.f, 0.f);
                while (row >= so[s]) s++;
            }
            float4 v = __ldg(xp + (size_t)i * 256);
            acc.x += v.x; acc.y += v.y; acc.z += v.z; acc.w += v.w;
        }
        float* dst = &g_segsum[s * C + cg * 4];
        atomicAdd(dst + 0, acc.x);
        atomicAdd(dst + 1, acc.y);
        atomicAdd(dst + 2, acc.z);
        atomicAdd(dst + 3, acc.w);
    }
}

// ---------------------------------------------------------------------------
// k2f: fused per-segment math. grid=S, 512 threads.
// ---------------------------------------------------------------------------
__global__ void __launch_bounds__(512) k2f(const int* __restrict__ o32,
                                           const float* __restrict__ W2,
                                           const float* __restrict__ b2,
                                           const float* __restrict__ W1,
                                           const float* __restrict__ b1,
                                           const float* __restrict__ gamma,
                                           const float* __restrict__ beta,
                                           const float* __restrict__ rm,
                                           const float* __restrict__ rv) {
    __shared__ float mean_s[C];
    __shared__ float h_s[C];
    __shared__ float red[512];
    int s = blockIdx.x, tid = threadIdx.x;
    int stride = (o32[1] == 0) ? 2 : 1;
    int oe = o32[s * stride];
    int ob = (s > 0) ? o32[(s - 1) * stride] : 0;
    float inv = 1.0f / (float)(oe - ob);
    if (tid < C) mean_s[tid] = g_segsum[s * C + tid] * inv;
    __syncthreads();

    int col0 = tid & 63;
    int kc = tid >> 6;

#pragma unroll 1
    for (int p = 0; p < 4; p++) {
        int col = p * 64 + col0;
        float a = 0.0f;
#pragma unroll 8
        for (int i = 0; i < 32; i++)
            a = fmaf(mean_s[kc * 32 + i], __ldg(&W2[(size_t)(kc * 32 + i) * C + col]), a);
        red[tid] = a;
        __syncthreads();
        if (tid < 64) {
            float t = red[tid];
#pragma unroll
            for (int j = 1; j < 8; j++) t += red[j * 64 + tid];
            int c0 = p * 64 + tid;
            h_s[c0] = fmaxf(t + __ldg(&b2[c0]), 0.0f);
        }
        __syncthreads();
    }

#pragma unroll 1
    for (int p = 0; p < 4; p++) {
        int col = p * 64 + col0;
        float a = 0.0f;
#pragma unroll 8
        for (int i = 0; i < 32; i++)
            a = fmaf(h_s[kc * 32 + i], __ldg(&W1[(size_t)(C + kc * 32 + i) * C + col]), a);
        red[tid] = a;
        __syncthreads();
        if (tid < 64) {
            float t = red[tid];
#pragma unroll
            for (int j = 1; j < 8; j++) t += red[j * 64 + tid];
            int c0 = p * 64 + tid;
            float sc = gamma[c0] * rsqrtf(rv[c0] + 1e-5f);
            g_ctab[s * C + c0] = (t + __ldg(&b1[c0])) * sc + beta[c0] - rm[c0] * sc;
        }
        __syncthreads();
    }
}

// ---------------------------------------------------------------------------
// k3: persistent fp16 mma.sync GEMM, 8 warps x (64x64) tiles (halves the LDS
// crossbar traffic vs 64x32), B + ctab resident in smem, two independent
// 128-thread halves synced by named barriers.
// smem: [so 128B][ctab 16K][A: 2 buf x 128 x AP halves][B: 4 x 64 x BP halves]
// ---------------------------------------------------------------------------
#define A_BYTES (BM * AP * 2)          // 18432
#define B_BYTES (BK * BP * 2)          // 33792 per chunk
#define CT_OFF 128
#define A_OFF (CT_OFF + 16384)         // 16512
#define B_OFF (A_OFF + 2 * A_BYTES)    // 53376
#define K3_SMEM (B_OFF + NCHUNK * B_BYTES)  // 188544

__global__ void __launch_bounds__(NT, 1) k3_mma(const float* __restrict__ x,
                                                const int* __restrict__ o32,
                                                float* __restrict__ out) {
    extern __shared__ char smem[];
    uint32_t sbase = smem_u32(smem);
    int* so_s = (int*)smem;
    float* ct_s = (float*)(smem + CT_OFF);
    __half* Asm = (__half*)(smem + A_OFF);
    const uint32_t aA = sbase + A_OFF;
    const uint32_t aB = sbase + B_OFF;

    int tid = threadIdx.x;
    int lane = tid & 31;
    int wid = tid >> 5;
    int wm = wid >> 2;   // 0..1 : which half (warps 0-3 low rows, 4-7 high)
    int wn = wid & 3;    // 0..3 : 64-col group
    int barid = 1 + wm;

    if (tid < S) {
        int stride = (o32[1] == 0) ? 2 : 1;
        so_s[tid] = o32[tid * stride];
    }
    // ctab -> smem (16 KB)
    {
        const float4* src = (const float4*)g_ctab;
        float4* dst = (float4*)ct_s;
#pragma unroll
        for (int j = 0; j < 4; j++) dst[tid + j * NT] = __ldg(&src[tid + j * NT]);
    }
    // ---- load ALL of B once (135 KB) ----
    {
        const char* src = (const char*)g_Bimg;
        for (int i = tid; i < (NCHUNK * B_BYTES) / 16; i += NT)
            CP_ASYNC16(aB + (uint32_t)(i * 16), src + i * 16);
        CP_COMMIT();
    }

    // A load geometry: 2 threads per row, 32 consecutive floats each.
    // tids 0-127 cover rows 0-63 (half 0's rows) -> half independence holds.
    int arow = tid >> 1;          // 0..127
    int acol = (tid & 1) * 32;    // 0 or 32

    uint32_t aoff[4];
#pragma unroll
    for (int ms = 0; ms < 4; ms++)
        aoff[ms] = (uint32_t)(((wm * 64 + ms * 16 + (lane & 15)) * AP + ((lane >> 4) << 3)) * 2);
    uint32_t boff[8];
#pragma unroll
    for (int ns = 0; ns < 8; ns++)
        boff[ns] = (uint32_t)(((lane & 15) * BP + wn * 64 + ns * 8) * 2);

    float acc[4][8][4];
#pragma unroll
    for (int i = 0; i < 4; i++)
#pragma unroll
        for (int j = 0; j < 8; j++)
#pragma unroll
            for (int r = 0; r < 4; r++) acc[i][j][r] = 0.0f;

    int ntile_local = 0;
    for (int t = blockIdx.x; t < NTILE; t += GRID) ntile_local++;
    int ncc = ntile_local * NCHUNK;
    if (ncc == 0) return;

    // prologue: load A for cc=0
    float4 pre[8];
    {
        const float* ag = x + (size_t)((size_t)blockIdx.x * BM + arow) * C + acol;
#pragma unroll
        for (int j = 0; j < 8; j++) pre[j] = __ldg((const float4*)(ag + j * 4));
        __half* dst = Asm + (size_t)arow * AP + acol;
#pragma unroll
        for (int j = 0; j < 8; j++) {
            __half2 a = __float22half2_rn(make_float2(pre[j].x, pre[j].y));
            __half2 b = __float22half2_rn(make_float2(pre[j].z, pre[j].w));
            *(uint2*)(dst + j * 4) = make_uint2(*(uint32_t*)&a, *(uint32_t*)&b);
        }
    }
    CP_WAIT0();
    __syncthreads();   // B + ctab + so + A(0) visible; halves drift after this

#pragma unroll 1
    for (int cc = 0; cc < ncc; cc++) {
        int chunk = cc & (NCHUNK - 1);
        int tile_i = cc >> 2;
        int buf = cc & 1;
        uint32_t abuf = aA + (uint32_t)(buf * A_BYTES);
        uint32_t bbuf = aB + (uint32_t)(chunk * B_BYTES);

        if (cc < ncc - 1) {
            int nchunk = (cc + 1) & (NCHUNK - 1);
            int ntile = (cc + 1) >> 2;
            size_t grow = (size_t)(blockIdx.x + ntile * GRID) * BM + arow;
            const float* ag = x + grow * C + nchunk * BK + acol;
#pragma unroll
            for (int j = 0; j < 8; j++) pre[j] = __ldg((const float4*)(ag + j * 4));
        }

        // ---- compute chunk against resident B (warp tile 64x64) ----
#pragma unroll
        for (int kk = 0; kk < BK; kk += 16) {
            uint32_t bf[8][2];
#pragma unroll
            for (int ns = 0; ns < 8; ns++)
                LDSM_X2_T(bf[ns][0], bf[ns][1], bbuf + boff[ns] + (uint32_t)(kk * BP * 2));
#pragma unroll
            for (int ms = 0; ms < 4; ms++) {
                uint32_t af[4];
                LDSM_X4(af[0], af[1], af[2], af[3], abuf + aoff[ms] + (uint32_t)(kk * 2));
#pragma unroll
                for (int ns = 0; ns < 8; ns++) MMA_F16(acc[ms][ns], af, bf[ns]);
            }
        }

        if (cc < ncc - 1) {
            __half* dst = Asm + (size_t)((buf ^ 1) * (A_BYTES / 2)) + (size_t)arow * AP + acol;
#pragma unroll
            for (int j = 0; j < 8; j++) {
                __half2 a = __float22half2_rn(make_float2(pre[j].x, pre[j].y));
                __half2 b = __float22half2_rn(make_float2(pre[j].z, pre[j].w));
                *(uint2*)(dst + j * 4) = make_uint2(*(uint32_t*)&a, *(uint32_t*)&b);
            }
        }
        BAR_HALF(barid);

        if (chunk == NCHUNK - 1) {
            int m0 = (blockIdx.x + tile_i * GRID) * BM;
            int r0 = lane >> 2;
            int cq = (lane & 3) * 2;
#pragma unroll
            for (int ms = 0; ms < 4; ms++) {
                int row = m0 + wm * 64 + ms * 16 + r0;
                int s0 = 0, s1 = 0;
                while (row >= so_s[s0]) s0++;
                while (row + 8 >= so_s[s1]) s1++;
                const float* ct0 = ct_s + s0 * C;
                const float* ct1 = ct_s + s1 * C;
                float* o0 = out + (size_t)row * C;
                float* o1 = out + (size_t)(row + 8) * C;
#pragma unroll
                for (int ns = 0; ns < 8; ns++) {
                    int col = wn * 64 + ns * 8 + cq;
                    float2 ca = *(const float2*)&ct0[col];
                    float2 cb = *(const float2*)&ct1[col];
                    float2 va, vb;
                    va.x = fmaxf(acc[ms][ns][0] + ca.x, 0.0f);
                    va.y = fmaxf(acc[ms][ns][1] + ca.y, 0.0f);
                    vb.x = fmaxf(acc[ms][ns][2] + cb.x, 0.0f);
                    vb.y = fmaxf(acc[ms][ns][3] + cb.y, 0.0f);
                    *(float2*)&o0[col] = va;
                    *(float2*)&o1[col] = vb;
                    acc[ms][ns][0] = 0.0f; acc[ms][ns][1] = 0.0f;
                    acc[ms][ns][2] = 0.0f; acc[ms][ns][3] = 0.0f;
                }
            }
        }
    }
}

// ---------------------------------------------------------------------------
extern "C" void kernel_launch(void* const* d_in, const int* in_sizes, int n_in,
                              void* d_out, int out_size) {
    const float* x     = (const float*)d_in[0];
    const int*   o     = (const int*)d_in[1];
    const float* W2    = (const float*)d_in[2];
    const float* b2    = (const float*)d_in[3];
    const float* W1    = (const float*)d_in[4];
    const float* b1    = (const float*)d_in[5];
    const float* gamma = (const float*)d_in[6];
    const float* beta  = (const float*)d_in[7];
    const float* rm    = (const float*)d_in[8];
    const float* rv    = (const float*)d_in[9];
    float* out = (float*)d_out;

    cudaFuncSetAttribute(k3_mma, cudaFuncAttributeMaxDynamicSharedMemorySize, K3_SMEM);

    kw_split<<<256, 256>>>(W1, gamma, rv);
    k1_segsum<<<NROWS / 128, 256>>>(x, o);
    k2f<<<S, 512>>>(o, W2, b2, W1, b1, gamma, beta, rm, rv);
    k3_mma<<<GRID, NT, K3_SMEM>>>(x, o, out);
}

// round 13
// speedup vs baseline: 1.3296x; 1.0329x over previous
#include <cuda_runtime.h>
#include <cuda_fp16.h>
#include <cstdint>
#include <math.h>

#define NROWS 262144
#define C 256
#define S 16

#define BM 128
#define BK 64
#define NCHUNK 4            // K=256 / BK
#define NT 256              // threads per CTA (8 warps, warp tile 64x64)
#define NTILE (NROWS / BM)  // 2048
#define GRID 148
#define AP 72               // A smem row stride in halves (64 + 8 pad)
#define BP 264              // B smem row stride in halves (256 + 8 pad)

// ---------------- scratch ---------------------------------------------------
__device__ float g_segsum[S * C];
__device__ float g_ctab[S * C];
// B image: [chunk][k=64][BP] fp16 of (W1a * diag(bn_scale)), exact smem layout
__device__ __half g_Bimg[NCHUNK * BK * BP];

// ---------------- helpers ---------------------------------------------------
__device__ __forceinline__ uint32_t smem_u32(const void* p) {
    uint32_t a;
    asm("{ .reg .u64 t; cvta.to.shared.u64 t, %1; cvt.u32.u64 %0, t; }" : "=r"(a) : "l"(p));
    return a;
}
#define CP_ASYNC16(dst, src) asm volatile("cp.async.cg.shared.global [%0], [%1], 16;" :: "r"(dst), "l"(src))
#define CP_COMMIT() asm volatile("cp.async.commit_group;" ::: "memory")
#define CP_WAIT0()  asm volatile("cp.async.wait_group 0;" ::: "memory")
#define BAR_HALF(id) asm volatile("bar.sync %0, 128;" :: "r"(id) : "memory")

#define LDSM_X4(r0, r1, r2, r3, addr) \
    asm volatile("ldmatrix.sync.aligned.m8n8.x4.shared.b16 {%0,%1,%2,%3}, [%4];" \
                 : "=r"(r0), "=r"(r1), "=r"(r2), "=r"(r3) : "r"(addr))
#define LDSM_X2_T(r0, r1, addr) \
    asm volatile("ldmatrix.sync.aligned.m8n8.x2.trans.shared.b16 {%0,%1}, [%2];" \
                 : "=r"(r0), "=r"(r1) : "r"(addr))

#define MMA_F16(d, a, b) \
    asm volatile("mma.sync.aligned.m16n8k16.row.col.f32.f16.f16.f32 " \
                 "{%0,%1,%2,%3}, {%4,%5,%6,%7}, {%8,%9}, {%0,%1,%2,%3};" \
                 : "+f"((d)[0]), "+f"((d)[1]), "+f"((d)[2]), "+f"((d)[3]) \
                 : "r"((a)[0]), "r"((a)[1]), "r"((a)[2]), "r"((a)[3]), "r"((b)[0]), "r"((b)[1]))

__device__ __forceinline__ uint2 cvt_f4_h4(float4 v) {
    __half2 a = __float22half2_rn(make_float2(v.x, v.y));
    __half2 b = __float22half2_rn(make_float2(v.z, v.w));
    return make_uint2(*(uint32_t*)&a, *(uint32_t*)&b);
}

// ---------------------------------------------------------------------------
// kw: W1a rows scaled by BN scale per column, fp16 chunk images; zeros segsum
__global__ void kw_split(const float* __restrict__ W1,
                         const float* __restrict__ gamma,
                         const float* __restrict__ rv) {
    int k = blockIdx.x;   // 0..255
    int n = threadIdx.x;  // 0..255
    if (k < S) g_segsum[k * C + n] = 0.0f;
    float sc = gamma[n] * rsqrtf(rv[n] + 1e-5f);
    float w = W1[k * C + n] * sc;
    int c = k >> 6, kk = k & 63;
    g_Bimg[(c * BK + kk) * BP + n] = __float2half_rn(w);
    if (n < BP - 256)
        g_Bimg[(c * BK + kk) * BP + 256 + n] = __float2half_rn(0.0f);
}

// ---------------------------------------------------------------------------
// k1: segment sums, float4 per thread, CTA-uniform fast path.
// ---------------------------------------------------------------------------
__global__ void __launch_bounds__(256) k1_segsum(const float* __restrict__ x,
                                                 const int* __restrict__ o32) {
    __shared__ int so[S];
    __shared__ float4 red[256];
    int tid = threadIdx.x;
    if (tid < S) {
        int stride = (o32[1] == 0) ? 2 : 1;
        so[tid] = o32[tid * stride];
    }
    __syncthreads();

    int g0 = blockIdx.x * 128;
    int cg = tid & 63;
    int rsub = tid >> 6;

    int sa = 0;
    while (g0 >= so[sa]) sa++;
    int sb = sa;
    while (g0 + 127 >= so[sb]) sb++;

    const float4* xp = (const float4*)x + (size_t)(g0 + rsub) * 64 + cg;
    float4 acc = make_float4(0.f, 0.f, 0.f, 0.f);

    if (sa == sb) {
#pragma unroll 4
        for (int i = 0; i < 32; i++) {
            float4 v = __ldg(xp + (size_t)i * 256);
            acc.x += v.x; acc.y += v.y; acc.z += v.z; acc.w += v.w;
        }
        red[tid] = acc;
        __syncthreads();
        if (tid < 64) {
            float4 a0 = red[tid], a1 = red[64 + tid], a2 = red[128 + tid], a3 = red[192 + tid];
            float* dst = &g_segsum[sa * C + tid * 4];
            atomicAdd(dst + 0, a0.x + a1.x + a2.x + a3.x);
            atomicAdd(dst + 1, a0.y + a1.y + a2.y + a3.y);
            atomicAdd(dst + 2, a0.z + a1.z + a2.z + a3.z);
            atomicAdd(dst + 3, a0.w + a1.w + a2.w + a3.w);
        }
    } else {
        int s = sa;
        while (g0 + rsub >= so[s]) s++;
        for (int i = 0; i < 32; i++) {
            int row = g0 + rsub + 4 * i;
            if (row >= so[s]) {
                float* dst = &g_segsum[s * C + cg * 4];
                atomicAdd(dst + 0, acc.x);
                atomicAdd(dst + 1, acc.y);
                atomicAdd(dst + 2, acc.z);
                atomicAdd(dst + 3, acc.w);
                acc = make_float4(0.f, 0.f, 0.f, 0.f);
                while (row >= so[s]) s++;
            }
            float4 v = __ldg(xp + (size_t)i * 256);
            acc.x += v.x; acc.y += v.y; acc.z += v.z; acc.w += v.w;
        }
        float* dst = &g_segsum[s * C + cg * 4];
        atomicAdd(dst + 0, acc.x);
        atomicAdd(dst + 1, acc.y);
        atomicAdd(dst + 2, acc.z);
        atomicAdd(dst + 3, acc.w);
    }
}

// ---------------------------------------------------------------------------
// k2f: fused per-segment math. grid=S, 512 threads.
// ---------------------------------------------------------------------------
__global__ void __launch_bounds__(512) k2f(const int* __restrict__ o32,
                                           const float* __restrict__ W2,
                                           const float* __restrict__ b2,
                                           const float* __restrict__ W1,
                                           const float* __restrict__ b1,
                                           const float* __restrict__ gamma,
                                           const float* __restrict__ beta,
                                           const float* __restrict__ rm,
                                           const float* __restrict__ rv) {
    __shared__ float mean_s[C];
    __shared__ float h_s[C];
    __shared__ float red[512];
    int s = blockIdx.x, tid = threadIdx.x;
    int stride = (o32[1] == 0) ? 2 : 1;
    int oe = o32[s * stride];
    int ob = (s > 0) ? o32[(s - 1) * stride] : 0;
    float inv = 1.0f / (float)(oe - ob);
    if (tid < C) mean_s[tid] = g_segsum[s * C + tid] * inv;
    __syncthreads();

    int col0 = tid & 63;
    int kc = tid >> 6;

#pragma unroll 1
    for (int p = 0; p < 4; p++) {
        int col = p * 64 + col0;
        float a = 0.0f;
#pragma unroll 8
        for (int i = 0; i < 32; i++)
            a = fmaf(mean_s[kc * 32 + i], __ldg(&W2[(size_t)(kc * 32 + i) * C + col]), a);
        red[tid] = a;
        __syncthreads();
        if (tid < 64) {
            float t = red[tid];
#pragma unroll
            for (int j = 1; j < 8; j++) t += red[j * 64 + tid];
            int c0 = p * 64 + tid;
            h_s[c0] = fmaxf(t + __ldg(&b2[c0]), 0.0f);
        }
        __syncthreads();
    }

#pragma unroll 1
    for (int p = 0; p < 4; p++) {
        int col = p * 64 + col0;
        float a = 0.0f;
#pragma unroll 8
        for (int i = 0; i < 32; i++)
            a = fmaf(h_s[kc * 32 + i], __ldg(&W1[(size_t)(C + kc * 32 + i) * C + col]), a);
        red[tid] = a;
        __syncthreads();
        if (tid < 64) {
            float t = red[tid];
#pragma unroll
            for (int j = 1; j < 8; j++) t += red[j * 64 + tid];
            int c0 = p * 64 + tid;
            float sc = gamma[c0] * rsqrtf(rv[c0] + 1e-5f);
            g_ctab[s * C + c0] = (t + __ldg(&b1[c0])) * sc + beta[c0] - rm[c0] * sc;
        }
        __syncthreads();
    }
}

// ---------------------------------------------------------------------------
// k3: persistent fp16 mma.sync GEMM, 8 warps x (64x64) tiles, B + ctab
// resident in smem, two independent 128-thread halves (named barriers),
// uniform-segment epilogue fast path with hoisted ct registers.
// smem: [so 128B][ctab 16K][A: 2 buf x 128 x AP halves][B: 4 x 64 x BP halves]
// ---------------------------------------------------------------------------
#define A_BYTES (BM * AP * 2)          // 18432
#define B_BYTES (BK * BP * 2)          // 33792 per chunk
#define CT_OFF 128
#define A_OFF (CT_OFF + 16384)         // 16512
#define B_OFF (A_OFF + 2 * A_BYTES)    // 53376
#define K3_SMEM (B_OFF + NCHUNK * B_BYTES)  // 188544

__global__ void __launch_bounds__(NT, 1) k3_mma(const float* __restrict__ x,
                                                const int* __restrict__ o32,
                                                float* __restrict__ out) {
    extern __shared__ char smem[];
    uint32_t sbase = smem_u32(smem);
    int* so_s = (int*)smem;
    float* ct_s = (float*)(smem + CT_OFF);
    __half* Asm = (__half*)(smem + A_OFF);
    const uint32_t aA = sbase + A_OFF;
    const uint32_t aB = sbase + B_OFF;

    int tid = threadIdx.x;
    int lane = tid & 31;
    int wid = tid >> 5;
    int wm = wid >> 2;   // 0..1 : which half (warps 0-3 low rows, 4-7 high)
    int wn = wid & 3;    // 0..3 : 64-col group
    int barid = 1 + wm;

    if (tid < S) {
        int stride = (o32[1] == 0) ? 2 : 1;
        so_s[tid] = o32[tid * stride];
    }
    // ctab -> smem (16 KB)
    {
        const float4* src = (const float4*)g_ctab;
        float4* dst = (float4*)ct_s;
#pragma unroll
        for (int j = 0; j < 4; j++) dst[tid + j * NT] = __ldg(&src[tid + j * NT]);
    }
    // ---- load ALL of B once (135 KB) ----
    {
        const char* src = (const char*)g_Bimg;
        for (int i = tid; i < (NCHUNK * B_BYTES) / 16; i += NT)
            CP_ASYNC16(aB + (uint32_t)(i * 16), src + i * 16);
        CP_COMMIT();
    }

    // A load geometry: 2 threads per row, 32 consecutive floats each.
    // tids 0-127 cover rows 0-63 (half 0's rows) -> half independence holds.
    int arow = tid >> 1;          // 0..127
    int acol = (tid & 1) * 32;    // 0 or 32

    uint32_t aoff[4];
#pragma unroll
    for (int ms = 0; ms < 4; ms++)
        aoff[ms] = (uint32_t)(((wm * 64 + ms * 16 + (lane & 15)) * AP + ((lane >> 4) << 3)) * 2);
    uint32_t boff[8];
#pragma unroll
    for (int ns = 0; ns < 8; ns++)
        boff[ns] = (uint32_t)(((lane & 15) * BP + wn * 64 + ns * 8) * 2);

    float acc[4][8][4];
#pragma unroll
    for (int i = 0; i < 4; i++)
#pragma unroll
        for (int j = 0; j < 8; j++)
#pragma unroll
            for (int r = 0; r < 4; r++) acc[i][j][r] = 0.0f;

    int ntile_local = 0;
    for (int t = blockIdx.x; t < NTILE; t += GRID) ntile_local++;
    int ncc = ntile_local * NCHUNK;
    if (ncc == 0) return;

    // prologue: load A for cc=0 (convert at load: 16 live regs, not 32)
    uint2 cvt[8];
    {
        const float* ag = x + (size_t)((size_t)blockIdx.x * BM + arow) * C + acol;
#pragma unroll
        for (int j = 0; j < 8; j++) cvt[j] = cvt_f4_h4(__ldg((const float4*)(ag + j * 4)));
        __half* dst = Asm + (size_t)arow * AP + acol;
#pragma unroll
        for (int j = 0; j < 8; j++) *(uint2*)(dst + j * 4) = cvt[j];
    }
    CP_WAIT0();
    __syncthreads();   // B + ctab + so + A(0) visible; halves drift after this

#pragma unroll 1
    for (int cc = 0; cc < ncc; cc++) {
        int chunk = cc & (NCHUNK - 1);
        int tile_i = cc >> 2;
        int buf = cc & 1;
        uint32_t abuf = aA + (uint32_t)(buf * A_BYTES);
        uint32_t bbuf = aB + (uint32_t)(chunk * B_BYTES);

        if (cc < ncc - 1) {
            int nchunk = (cc + 1) & (NCHUNK - 1);
            int ntile = (cc + 1) >> 2;
            size_t grow = (size_t)(blockIdx.x + ntile * GRID) * BM + arow;
            const float* ag = x + grow * C + nchunk * BK + acol;
#pragma unroll
            for (int j = 0; j < 8; j++) cvt[j] = cvt_f4_h4(__ldg((const float4*)(ag + j * 4)));
        }

        // ---- compute chunk against resident B (warp tile 64x64) ----
#pragma unroll
        for (int kk = 0; kk < BK; kk += 16) {
            uint32_t bf[8][2];
#pragma unroll
            for (int ns = 0; ns < 8; ns++)
                LDSM_X2_T(bf[ns][0], bf[ns][1], bbuf + boff[ns] + (uint32_t)(kk * BP * 2));
#pragma unroll
            for (int ms = 0; ms < 4; ms++) {
                uint32_t af[4];
                LDSM_X4(af[0], af[1], af[2], af[3], abuf + aoff[ms] + (uint32_t)(kk * 2));
#pragma unroll
                for (int ns = 0; ns < 8; ns++) MMA_F16(acc[ms][ns], af, bf[ns]);
            }
        }

        if (cc < ncc - 1) {
            __half* dst = Asm + (size_t)((buf ^ 1) * (A_BYTES / 2)) + (size_t)arow * AP + acol;
#pragma unroll
            for (int j = 0; j < 8; j++) *(uint2*)(dst + j * 4) = cvt[j];
        }
        BAR_HALF(barid);

        if (chunk == NCHUNK - 1) {
            int m0 = (blockIdx.x + tile_i * GRID) * BM;
            int rowbase = m0 + wm * 64;
            int r0 = lane >> 2;
            int cq = (lane & 3) * 2;
            // segment of first and last row of this 64-row half-tile
            int sA = 0;
            while (rowbase >= so_s[sA]) sA++;
            int sB = sA;
            while (rowbase + 63 >= so_s[sB]) sB++;

            if (sA == sB) {
                // ---- uniform-segment fast path: hoist ct once per lane ----
                const float* ctp = ct_s + sA * C + wn * 64 + cq;
                float2 ct[8];
#pragma unroll
                for (int ns = 0; ns < 8; ns++) ct[ns] = *(const float2*)&ctp[ns * 8];
#pragma unroll
                for (int ms = 0; ms < 4; ms++) {
                    int row = rowbase + ms * 16 + r0;
                    float* o0 = out + (size_t)row * C + wn * 64 + cq;
                    float* o1 = o0 + 8 * C;
#pragma unroll
                    for (int ns = 0; ns < 8; ns++) {
                        float2 va, vb;
                        va.x = fmaxf(acc[ms][ns][0] + ct[ns].x, 0.0f);
                        va.y = fmaxf(acc[ms][ns][1] + ct[ns].y, 0.0f);
                        vb.x = fmaxf(acc[ms][ns][2] + ct[ns].x, 0.0f);
                        vb.y = fmaxf(acc[ms][ns][3] + ct[ns].y, 0.0f);
                        *(float2*)&o0[ns * 8] = va;
                        *(float2*)&o1[ns * 8] = vb;
                        acc[ms][ns][0] = 0.0f; acc[ms][ns][1] = 0.0f;
                        acc[ms][ns][2] = 0.0f; acc[ms][ns][3] = 0.0f;
                    }
                }
            } else {
                // ---- boundary tile (rare): per-row segment lookup ----
#pragma unroll
                for (int ms = 0; ms < 4; ms++) {
                    int row = rowbase + ms * 16 + r0;
                    int s0 = 0, s1 = 0;
                    while (row >= so_s[s0]) s0++;
                    while (row + 8 >= so_s[s1]) s1++;
                    const float* ct0 = ct_s + s0 * C;
                    const float* ct1 = ct_s + s1 * C;
                    float* o0 = out + (size_t)row * C;
                    float* o1 = out + (size_t)(row + 8) * C;
#pragma unroll
                    for (int ns = 0; ns < 8; ns++) {
                        int col = wn * 64 + ns * 8 + cq;
                        float2 ca = *(const float2*)&ct0[col];
                        float2 cb = *(const float2*)&ct1[col];
                        float2 va, vb;
                        va.x = fmaxf(acc[ms][ns][0] + ca.x, 0.0f);
                        va.y = fmaxf(acc[ms][ns][1] + ca.y, 0.0f);
                        vb.x = fmaxf(acc[ms][ns][2] + cb.x, 0.0f);
                        vb.y = fmaxf(acc[ms][ns][3] + cb.y, 0.0f);
                        *(float2*)&o0[col] = va;
                        *(float2*)&o1[col] = vb;
                        acc[ms][ns][0] = 0.0f; acc[ms][ns][1] = 0.0f;
                        acc[ms][ns][2] = 0.0f; acc[ms][ns][3] = 0.0f;
                    }
                }
            }
        }
    }
}

// ---------------------------------------------------------------------------
extern "C" void kernel_launch(void* const* d_in, const int* in_sizes, int n_in,
                              void* d_out, int out_size) {
    const float* x     = (const float*)d_in[0];
    const int*   o     = (const int*)d_in[1];
    const float* W2    = (const float*)d_in[2];
    const float* b2    = (const float*)d_in[3];
    const float* W1    = (const float*)d_in[4];
    const float* b1    = (const float*)d_in[5];
    const float* gamma = (const float*)d_in[6];
    const float* beta  = (const float*)d_in[7];
    const float* rm    = (const float*)d_in[8];
    const float* rv    = (const float*)d_in[9];
    float* out = (float*)d_out;

    cudaFuncSetAttribute(k3_mma, cudaFuncAttributeMaxDynamicSharedMemorySize, K3_SMEM);

    kw_split<<<256, 256>>>(W1, gamma, rv);
    k1_segsum<<<NROWS / 128, 256>>>(x, o);
    k2f<<<S, 512>>>(o, W2, b2, W1, b1, gamma, beta, rm, rv);
    k3_mma<<<GRID, NT, K3_SMEM>>>(x, o, out);
}